// round 1
// baseline (speedup 1.0000x reference)
#include <cuda_runtime.h>
#include <math.h>

#define NB 4
#define NP 2048
#define ND 64
#define EPS_F 0.1f
#define THRESH_F 0.1f
#define MAX_ITER 50

static __device__ float g_C[(size_t)NB * NP * NP];   // 64 MB cost matrix
static __device__ float g_u[NB * NP];
static __device__ float g_v[NB * NP];
static __device__ float g_errpart[1024];
static __device__ float g_costpart[1024];
static __device__ int   g_done;

__device__ __forceinline__ float inv_eps() { return 1.0f / EPS_F; }

// ---------------------------------------------------------------------------
// init: zero u, v, done (must be re-done every graph replay)
// ---------------------------------------------------------------------------
__global__ void k_init() {
    int t = blockIdx.x * blockDim.x + threadIdx.x;
    if (t < NB * NP) { g_u[t] = 0.0f; g_v[t] = 0.0f; }
    if (t == 0) g_done = 0;
}

// ---------------------------------------------------------------------------
// C[b][i][j] = ||x_i||^2 + ||y_j||^2 - 2 * <x_i, y_j>
// grid (32, 32, 4), 256 threads, 64x64 output tile per block
// ---------------------------------------------------------------------------
__global__ void k_cost(const float* __restrict__ x, const float* __restrict__ y) {
    __shared__ float xs[ND][68];   // [d][i], padded (68*4=272B = 17*16B, f4-aligned)
    __shared__ float ys[ND][68];   // [d][j]
    __shared__ float nx[64], ny[64];

    int b  = blockIdx.z;
    int i0 = blockIdx.y * 64;
    int j0 = blockIdx.x * 64;
    int tid = threadIdx.x;

    const float* xp = x + ((size_t)b * NP + i0) * ND;
    const float* yp = y + ((size_t)b * NP + j0) * ND;

    // coalesced gmem load (consecutive threads -> consecutive d)
    for (int idx = tid; idx < 64 * ND; idx += 256) {
        int r = idx >> 6;
        int d = idx & 63;
        xs[d][r] = xp[r * ND + d];
        ys[d][r] = yp[r * ND + d];
    }
    __syncthreads();

    if (tid < 64) {
        float s = 0.0f;
        #pragma unroll 16
        for (int d = 0; d < ND; d++) { float v = xs[d][tid]; s = fmaf(v, v, s); }
        nx[tid] = s;
    } else if (tid < 128) {
        int j = tid - 64;
        float s = 0.0f;
        #pragma unroll 16
        for (int d = 0; d < ND; d++) { float v = ys[d][j]; s = fmaf(v, v, s); }
        ny[j] = s;
    }
    __syncthreads();

    int tx = tid & 15, ty = tid >> 4;
    float acc[4][4] = {};
    #pragma unroll 16
    for (int d = 0; d < ND; d++) {
        float4 xr = *(const float4*)&xs[d][ty * 4];
        float4 yr = *(const float4*)&ys[d][tx * 4];
        float xa[4] = {xr.x, xr.y, xr.z, xr.w};
        float ya[4] = {yr.x, yr.y, yr.z, yr.w};
        #pragma unroll
        for (int a = 0; a < 4; a++)
            #pragma unroll
            for (int c = 0; c < 4; c++)
                acc[a][c] = fmaf(xa[a], ya[c], acc[a][c]);
    }

    #pragma unroll
    for (int a = 0; a < 4; a++) {
        int i = i0 + ty * 4 + a;
        size_t base = ((size_t)b * NP + i) * NP + j0 + tx * 4;
        float4 o;
        o.x = nx[ty * 4 + a] + ny[tx * 4 + 0] - 2.0f * acc[a][0];
        o.y = nx[ty * 4 + a] + ny[tx * 4 + 1] - 2.0f * acc[a][1];
        o.z = nx[ty * 4 + a] + ny[tx * 4 + 2] - 2.0f * acc[a][2];
        o.w = nx[ty * 4 + a] + ny[tx * 4 + 3] - 2.0f * acc[a][3];
        *(float4*)&g_C[base] = o;
    }
}

// ---------------------------------------------------------------------------
// u update: u_new_i = eps*(log_mu - LSE_j((v_j - C_ij)/eps))
// grid 1024 blocks x 256 threads; 1 warp per row (8 rows/block)
// also writes per-block err partial  sum_i |u_new - u_old|
// ---------------------------------------------------------------------------
__global__ void k_urow() {
    if (g_done) return;
    __shared__ float vs[NP];     // v * inv_eps
    __shared__ float werr[8];

    int tid = threadIdx.x;
    int rowbase = blockIdx.x * 8;
    int b = rowbase >> 11;

    for (int j = tid; j < NP; j += 256) vs[j] = g_v[b * NP + j] * inv_eps();
    __syncthreads();

    int w = tid >> 5, lane = tid & 31;
    int row = rowbase + w;                       // = b*NP + i
    const float* Cr = g_C + (size_t)row * NP;

    float m = -INFINITY, s = 0.0f;
    #pragma unroll 1
    for (int c = 0; c < 4; c++) {
        float a[16];
        #pragma unroll
        for (int k = 0; k < 16; k++) {
            int j = (c * 16 + k) * 32 + lane;
            a[k] = fmaf(Cr[j], -inv_eps(), vs[j]);
        }
        float cm = a[0];
        #pragma unroll
        for (int k = 1; k < 16; k++) cm = fmaxf(cm, a[k]);
        float nm = fmaxf(m, cm);
        s *= __expf(m - nm);
        #pragma unroll
        for (int k = 0; k < 16; k++) s += __expf(a[k] - nm);
        m = nm;
    }
    // warp LSE combine
    #pragma unroll
    for (int off = 16; off; off >>= 1) {
        float om = __shfl_down_sync(0xffffffffu, m, off);
        float os = __shfl_down_sync(0xffffffffu, s, off);
        float nm = fmaxf(m, om);
        s = s * __expf(m - nm) + os * __expf(om - nm);
        m = nm;
    }
    if (lane == 0) {
        float lse = m + logf(s);
        float lmu = logf(1.0f / (float)NP + 1e-8f);
        float un  = EPS_F * (lmu - lse);
        float uo  = g_u[row];
        g_u[row]  = un;
        werr[w]   = fabsf(un - uo);
    }
    __syncthreads();
    if (tid == 0) {
        float e = 0.0f;
        #pragma unroll
        for (int k = 0; k < 8; k++) e += werr[k];
        g_errpart[blockIdx.x] = e;
    }
}

// ---------------------------------------------------------------------------
// v update: v_new_j = eps*(log_nu - LSE_i((u_i - C_ij)/eps))    (u = new u)
// grid 256 blocks x 256 threads; block = (b, 32-column group), warps split i.
// block 0 additionally reduces err partials and sets g_done (deterministic).
// ---------------------------------------------------------------------------
__global__ void k_vcol() {
    if (g_done) return;
    __shared__ float us[NP];
    __shared__ float sm[8][33], ss[8][33];
    __shared__ float red[256];

    int tid = threadIdx.x;

    if (blockIdx.x == 0) {
        float e = 0.0f;
        for (int k = tid; k < 1024; k += 256) e += g_errpart[k];
        red[tid] = e;
        __syncthreads();
        for (int st = 128; st; st >>= 1) {
            if (tid < st) red[tid] += red[tid + st];
            __syncthreads();
        }
        if (tid == 0) {
            if (red[0] * (1.0f / (float)NB) < THRESH_F) g_done = 1;
        }
    }

    int task = blockIdx.x;
    int b  = task >> 6;
    int j0 = (task & 63) * 32;

    for (int i = tid; i < NP; i += 256) us[i] = g_u[b * NP + i] * inv_eps();
    __syncthreads();

    int w = tid >> 5, lane = tid & 31;
    const float* Cb = g_C + (size_t)b * NP * NP + j0 + lane;
    int ibase = w * 256;

    float m = -INFINITY, s = 0.0f;
    #pragma unroll 1
    for (int c = 0; c < 16; c++) {
        float a[16];
        #pragma unroll
        for (int k = 0; k < 16; k++) {
            int i = ibase + c * 16 + k;
            a[k] = fmaf(Cb[(size_t)i * NP], -inv_eps(), us[i]);
        }
        float cm = a[0];
        #pragma unroll
        for (int k = 1; k < 16; k++) cm = fmaxf(cm, a[k]);
        float nm = fmaxf(m, cm);
        s *= __expf(m - nm);
        #pragma unroll
        for (int k = 0; k < 16; k++) s += __expf(a[k] - nm);
        m = nm;
    }
    sm[w][lane] = m;
    ss[w][lane] = s;
    __syncthreads();

    if (w == 0) {
        float M = sm[0][lane];
        #pragma unroll
        for (int k = 1; k < 8; k++) M = fmaxf(M, sm[k][lane]);
        float S = 0.0f;
        #pragma unroll
        for (int k = 0; k < 8; k++) S += ss[k][lane] * __expf(sm[k][lane] - M);
        float lse = M + logf(S);
        float lnu = logf(1.0f / (float)NP + 1e-8f);
        g_v[b * NP + j0 + lane] = EPS_F * (lnu - lse);
    }
}

// ---------------------------------------------------------------------------
// final: cost partials  sum_ij exp((u_i + v_j - C)/eps) * C
// grid 1024 x 256, warp per row
// ---------------------------------------------------------------------------
__global__ void k_final() {
    __shared__ float vs[NP];
    __shared__ float wsum[8];

    int tid = threadIdx.x;
    int rowbase = blockIdx.x * 8;
    int b = rowbase >> 11;

    for (int j = tid; j < NP; j += 256) vs[j] = g_v[b * NP + j] * inv_eps();
    __syncthreads();

    int w = tid >> 5, lane = tid & 31;
    int row = rowbase + w;
    const float* Cr = g_C + (size_t)row * NP;
    float uie = g_u[row] * inv_eps();

    float acc = 0.0f;
    #pragma unroll 4
    for (int t = 0; t < 64; t++) {
        int j = t * 32 + lane;
        float Cv = Cr[j];
        float e  = __expf(fmaf(Cv, -inv_eps(), uie + vs[j]));
        acc = fmaf(e, Cv, acc);
    }
    #pragma unroll
    for (int off = 16; off; off >>= 1)
        acc += __shfl_down_sync(0xffffffffu, acc, off);
    if (lane == 0) wsum[w] = acc;
    __syncthreads();
    if (tid == 0) {
        float e = 0.0f;
        #pragma unroll
        for (int k = 0; k < 8; k++) e += wsum[k];
        g_costpart[blockIdx.x] = e;
    }
}

__global__ void k_reduce(float* out) {
    __shared__ float red[256];
    int tid = threadIdx.x;
    float e = 0.0f;
    for (int k = tid; k < 1024; k += 256) e += g_costpart[k];
    red[tid] = e;
    __syncthreads();
    for (int st = 128; st; st >>= 1) {
        if (tid < st) red[tid] += red[tid + st];
        __syncthreads();
    }
    if (tid == 0) out[0] = red[0] * (1.0f / (float)NB);
}

// ---------------------------------------------------------------------------
extern "C" void kernel_launch(void* const* d_in, const int* in_sizes, int n_in,
                              void* d_out, int out_size) {
    const float* x = (const float*)d_in[0];
    const float* y = (const float*)d_in[1];
    float* out = (float*)d_out;

    k_init<<<32, 256>>>();
    dim3 gc(32, 32, 4);
    k_cost<<<gc, 256>>>(x, y);
    for (int it = 0; it < MAX_ITER; ++it) {
        k_urow<<<1024, 256>>>();
        k_vcol<<<256, 256>>>();
    }
    k_final<<<1024, 256>>>();
    k_reduce<<<1, 256>>>(out);
}

// round 4
// speedup vs baseline: 1.3975x; 1.3975x over previous
#include <cuda_runtime.h>
#include <math.h>

#define NB 4
#define NP 2048
#define ND 64
#define EPS_F 0.1f
#define THRESH_F 0.1f
#define MAX_ITER 50

static __device__ float g_C[(size_t)NB * NP * NP];   // 64 MB cost matrix
static __device__ float g_u[NB * NP];
static __device__ float g_v[NB * NP];
static __device__ float g_errpart[1024];
static __device__ float g_costpart[1024];
static __device__ int   g_done;

__device__ __forceinline__ float inv_eps() { return 1.0f / EPS_F; }

// ---------------------------------------------------------------------------
// init: zero u, v; errpart = huge (first-iteration done check must be false)
// ---------------------------------------------------------------------------
__global__ void k_init() {
    int t = blockIdx.x * blockDim.x + threadIdx.x;
    if (t < NB * NP) { g_u[t] = 0.0f; g_v[t] = 0.0f; }
    if (t < 1024) g_errpart[t] = 1.0e30f;
    if (t == 0) g_done = 0;
}

// ---------------------------------------------------------------------------
// C[b][i][j] = ||x_i||^2 + ||y_j||^2 - 2 * <x_i, y_j>
// grid (32, 32, 4), 256 threads, 64x64 output tile per block
// ---------------------------------------------------------------------------
__global__ void k_cost(const float* __restrict__ x, const float* __restrict__ y) {
    __shared__ __align__(16) float xs[ND][68];
    __shared__ __align__(16) float ys[ND][68];
    __shared__ float nx[64], ny[64];

    int b  = blockIdx.z;
    int i0 = blockIdx.y * 64;
    int j0 = blockIdx.x * 64;
    int tid = threadIdx.x;

    const float* xp = x + ((size_t)b * NP + i0) * ND;
    const float* yp = y + ((size_t)b * NP + j0) * ND;

    for (int idx = tid; idx < 64 * ND; idx += 256) {
        int r = idx >> 6;
        int d = idx & 63;
        xs[d][r] = xp[r * ND + d];
        ys[d][r] = yp[r * ND + d];
    }
    __syncthreads();

    if (tid < 64) {
        float s = 0.0f;
        #pragma unroll 16
        for (int d = 0; d < ND; d++) { float v = xs[d][tid]; s = fmaf(v, v, s); }
        nx[tid] = s;
    } else if (tid < 128) {
        int j = tid - 64;
        float s = 0.0f;
        #pragma unroll 16
        for (int d = 0; d < ND; d++) { float v = ys[d][j]; s = fmaf(v, v, s); }
        ny[j] = s;
    }
    __syncthreads();

    int tx = tid & 15, ty = tid >> 4;
    float acc[4][4] = {};
    #pragma unroll 16
    for (int d = 0; d < ND; d++) {
        float4 xr = *(const float4*)&xs[d][ty * 4];
        float4 yr = *(const float4*)&ys[d][tx * 4];
        float xa[4] = {xr.x, xr.y, xr.z, xr.w};
        float ya[4] = {yr.x, yr.y, yr.z, yr.w};
        #pragma unroll
        for (int a = 0; a < 4; a++)
            #pragma unroll
            for (int c = 0; c < 4; c++)
                acc[a][c] = fmaf(xa[a], ya[c], acc[a][c]);
    }

    #pragma unroll
    for (int a = 0; a < 4; a++) {
        int i = i0 + ty * 4 + a;
        size_t base = ((size_t)b * NP + i) * NP + j0 + tx * 4;
        float4 o;
        o.x = nx[ty * 4 + a] + ny[tx * 4 + 0] - 2.0f * acc[a][0];
        o.y = nx[ty * 4 + a] + ny[tx * 4 + 1] - 2.0f * acc[a][1];
        o.z = nx[ty * 4 + a] + ny[tx * 4 + 2] - 2.0f * acc[a][2];
        o.w = nx[ty * 4 + a] + ny[tx * 4 + 3] - 2.0f * acc[a][3];
        *(float4*)&g_C[base] = o;
    }
}

// ---------------------------------------------------------------------------
// u update: u_new_i = eps*(log_mu - LSE_j((v_j - C_ij)/eps))
// grid 1024 x 256; warp per row; float4 loads.
// Each block ALSO deterministically reduces last iteration's err partials and
// writes g_done (same value from every block -> race-free "done entering step")
// ---------------------------------------------------------------------------
__global__ __launch_bounds__(256) void k_urow() {
    __shared__ __align__(16) float vs[NP];
    __shared__ float red[256];
    __shared__ float werr[8];
    __shared__ int   sdone;

    int tid = threadIdx.x;
    int rowbase = blockIdx.x * 8;
    int b = rowbase >> 11;

    // overlap v-load with err reduction
    for (int j = tid; j < NP; j += 256) vs[j] = g_v[b * NP + j] * inv_eps();
    {
        float e = 0.0f;
        #pragma unroll
        for (int k = 0; k < 4; k++) e += g_errpart[tid + k * 256];
        red[tid] = e;
    }
    __syncthreads();
    #pragma unroll
    for (int st = 128; st; st >>= 1) {
        if (tid < st) red[tid] += red[tid + st];
        __syncthreads();
    }
    if (tid == 0) {
        int d = (red[0] * (1.0f / (float)NB) < THRESH_F) ? 1 : 0;
        sdone = d;
        g_done = d;       // every block writes the identical value
    }
    __syncthreads();
    if (sdone) return;    // frozen: leave u and errpart untouched

    int w = tid >> 5, lane = tid & 31;
    int row = rowbase + w;
    const float4* Cr = (const float4*)(g_C + (size_t)row * NP);
    const float4* vv = (const float4*)vs;

    float m = -INFINITY, s = 0.0f;
    #pragma unroll 1
    for (int c = 0; c < 4; c++) {
        float a[16];
        #pragma unroll
        for (int k = 0; k < 4; k++) {
            int q = (c * 4 + k) * 32 + lane;
            float4 Cq = Cr[q];
            float4 vq = vv[q];
            a[k * 4 + 0] = fmaf(Cq.x, -inv_eps(), vq.x);
            a[k * 4 + 1] = fmaf(Cq.y, -inv_eps(), vq.y);
            a[k * 4 + 2] = fmaf(Cq.z, -inv_eps(), vq.z);
            a[k * 4 + 3] = fmaf(Cq.w, -inv_eps(), vq.w);
        }
        float cm = a[0];
        #pragma unroll
        for (int k = 1; k < 16; k++) cm = fmaxf(cm, a[k]);
        float nm = fmaxf(m, cm);
        s *= __expf(m - nm);
        #pragma unroll
        for (int k = 0; k < 16; k++) s += __expf(a[k] - nm);
        m = nm;
    }
    #pragma unroll
    for (int off = 16; off; off >>= 1) {
        float om = __shfl_down_sync(0xffffffffu, m, off);
        float os = __shfl_down_sync(0xffffffffu, s, off);
        float nm = fmaxf(m, om);
        s = s * __expf(m - nm) + os * __expf(om - nm);
        m = nm;
    }
    if (lane == 0) {
        float lse = m + logf(s);
        float lmu = logf(1.0f / (float)NP + 1e-8f);
        float un  = EPS_F * (lmu - lse);
        float uo  = g_u[row];
        g_u[row]  = un;
        werr[w]   = fabsf(un - uo);
    }
    __syncthreads();
    if (tid == 0) {
        float e = 0.0f;
        #pragma unroll
        for (int k = 0; k < 8; k++) e += werr[k];
        g_errpart[blockIdx.x] = e;
    }
}

// ---------------------------------------------------------------------------
// v update: v_new_j = eps*(log_nu - LSE_i((u_i - C_ij)/eps))    (u = new u)
// grid 256 blocks x 1024 threads; block = (b, 32-col group); 32 warps split i
// (64 rows each). Warp partials (m,s) combined in smem by warp 0.
// ---------------------------------------------------------------------------
__global__ __launch_bounds__(1024, 2) void k_vcol() {
    if (*(volatile int*)&g_done) return; // value written by this step's k_urow
    __shared__ float us[NP];
    __shared__ float sm[32][33], ss[32][33];

    int tid = threadIdx.x;
    int b  = blockIdx.x >> 6;
    int j0 = (blockIdx.x & 63) * 32;

    for (int i = tid; i < NP; i += 1024) us[i] = g_u[b * NP + i] * inv_eps();
    __syncthreads();

    int w = tid >> 5, lane = tid & 31;
    const float* Cb = g_C + (size_t)b * NP * NP + j0 + lane;
    int ibase = w * 64;

    float m = -INFINITY, s = 0.0f;
    #pragma unroll 1
    for (int c = 0; c < 8; c++) {
        float a[8];
        #pragma unroll
        for (int k = 0; k < 8; k++) {
            int i = ibase + c * 8 + k;
            a[k] = fmaf(Cb[(size_t)i * NP], -inv_eps(), us[i]);
        }
        float cm = a[0];
        #pragma unroll
        for (int k = 1; k < 8; k++) cm = fmaxf(cm, a[k]);
        float nm = fmaxf(m, cm);
        s *= __expf(m - nm);
        #pragma unroll
        for (int k = 0; k < 8; k++) s += __expf(a[k] - nm);
        m = nm;
    }
    sm[w][lane] = m;
    ss[w][lane] = s;
    __syncthreads();

    if (w == 0) {
        float M = sm[0][lane];
        #pragma unroll
        for (int k = 1; k < 32; k++) M = fmaxf(M, sm[k][lane]);
        float S = 0.0f;
        #pragma unroll
        for (int k = 0; k < 32; k++) S += ss[k][lane] * __expf(sm[k][lane] - M);
        float lse = M + logf(S);
        float lnu = logf(1.0f / (float)NP + 1e-8f);
        g_v[b * NP + j0 + lane] = EPS_F * (lnu - lse);
    }
}

// ---------------------------------------------------------------------------
// final: cost partials  sum_ij exp((u_i + v_j - C)/eps) * C ; float4 loads
// ---------------------------------------------------------------------------
__global__ __launch_bounds__(256) void k_final() {
    __shared__ __align__(16) float vs[NP];
    __shared__ float wsum[8];

    int tid = threadIdx.x;
    int rowbase = blockIdx.x * 8;
    int b = rowbase >> 11;

    for (int j = tid; j < NP; j += 256) vs[j] = g_v[b * NP + j] * inv_eps();
    __syncthreads();

    int w = tid >> 5, lane = tid & 31;
    int row = rowbase + w;
    const float4* Cr = (const float4*)(g_C + (size_t)row * NP);
    const float4* vv = (const float4*)vs;
    float uie = g_u[row] * inv_eps();

    float acc = 0.0f;
    #pragma unroll 4
    for (int t = 0; t < 16; t++) {
        int q = t * 32 + lane;
        float4 Cq = Cr[q];
        float4 vq = vv[q];
        float e0 = __expf(fmaf(Cq.x, -inv_eps(), uie + vq.x));
        float e1 = __expf(fmaf(Cq.y, -inv_eps(), uie + vq.y));
        float e2 = __expf(fmaf(Cq.z, -inv_eps(), uie + vq.z));
        float e3 = __expf(fmaf(Cq.w, -inv_eps(), uie + vq.w));
        acc = fmaf(e0, Cq.x, acc);
        acc = fmaf(e1, Cq.y, acc);
        acc = fmaf(e2, Cq.z, acc);
        acc = fmaf(e3, Cq.w, acc);
    }
    #pragma unroll
    for (int off = 16; off; off >>= 1)
        acc += __shfl_down_sync(0xffffffffu, acc, off);
    if (lane == 0) wsum[w] = acc;
    __syncthreads();
    if (tid == 0) {
        float e = 0.0f;
        #pragma unroll
        for (int k = 0; k < 8; k++) e += wsum[k];
        g_costpart[blockIdx.x] = e;
    }
}

__global__ void k_reduce(float* out) {
    __shared__ float red[256];
    int tid = threadIdx.x;
    float e = 0.0f;
    for (int k = tid; k < 1024; k += 256) e += g_costpart[k];
    red[tid] = e;
    __syncthreads();
    for (int st = 128; st; st >>= 1) {
        if (tid < st) red[tid] += red[tid + st];
        __syncthreads();
    }
    if (tid == 0) out[0] = red[0] * (1.0f / (float)NB);
}

// ---------------------------------------------------------------------------
extern "C" void kernel_launch(void* const* d_in, const int* in_sizes, int n_in,
                              void* d_out, int out_size) {
    const float* x = (const float*)d_in[0];
    const float* y = (const float*)d_in[1];
    float* out = (float*)d_out;

    k_init<<<32, 256>>>();
    dim3 gc(32, 32, 4);
    k_cost<<<gc, 256>>>(x, y);
    for (int it = 0; it < MAX_ITER; ++it) {
        k_urow<<<1024, 256>>>();
        k_vcol<<<256, 1024>>>();
    }
    k_final<<<1024, 256>>>();
    k_reduce<<<1, 256>>>(out);
}